// round 6
// baseline (speedup 1.0000x reference)
#include <cuda_runtime.h>
#include <cstdint>

// Problem shape (fixed by the reference)
#define BB 64
#define SS 2048
#define DD 256
#define TOTROWS (BB * SS)        // 131072 flat (b,s) rows
#define GRIDX 152                // one CTA per SM on GB300
#define NST 6                    // smem ring stages
#define TROWS 32                 // rows per tile
#define TBYTES (TROWS * DD * 4)  // 32 KB per tile

// Dynamic smem layout (bytes from base)
#define SM_FEAT 0
#define SM_SUM  (NST * TBYTES)          // 196608: float4[256]
#define SM_MAX  (SM_SUM + 4096)         // float4[256]
#define SM_CNT  (SM_MAX + 4096)         // float[4]
#define SM_LAST (SM_CNT + 16)           // int
#define SM_MBAR (SM_LAST + 16)          // NST x 8B mbarriers
#define SM_TOTAL (SM_MBAR + NST * 8)

// Global scratch (zero-init; reset by finalizer each call for graph replays)
__device__ float    g_sum [BB * DD];
__device__ unsigned g_maxo[BB * DD];
__device__ float    g_cnt [BB];
__device__ int      g_rows[BB];

__device__ __forceinline__ float neg_inf() { return __int_as_float(0xff800000); }
__device__ __forceinline__ unsigned f2o(float f) {
    unsigned u = __float_as_uint(f);
    return (u & 0x80000000u) ? ~u : (u | 0x80000000u);
}
__device__ __forceinline__ float o2f(unsigned u) {
    return __uint_as_float((u & 0x80000000u) ? (u & 0x7fffffffu) : ~u);
}

__device__ __forceinline__ uint32_t smem_u32(const void* p) {
    uint32_t a;
    asm("{ .reg .u64 t; cvta.to.shared.u64 t, %1; cvt.u32.u64 %0, t; }" : "=r"(a) : "l"(p));
    return a;
}
__device__ __forceinline__ void mbar_init(uint32_t bar, uint32_t cnt) {
    asm volatile("mbarrier.init.shared.b64 [%0], %1;" :: "r"(bar), "r"(cnt) : "memory");
}
__device__ __forceinline__ void mbar_expect_tx(uint32_t bar, uint32_t bytes) {
    asm volatile("mbarrier.arrive.expect_tx.shared.b64 _, [%0], %1;"
                 :: "r"(bar), "r"(bytes) : "memory");
}
__device__ __forceinline__ void mbar_wait(uint32_t bar, uint32_t parity) {
    asm volatile(
        "{\n\t"
        ".reg .pred P;\n\t"
        "WL_%=:\n\t"
        "mbarrier.try_wait.parity.acquire.cta.shared::cta.b64 P, [%0], %1, 0x989680;\n\t"
        "@P bra.uni WD_%=;\n\t"
        "bra.uni WL_%=;\n\t"
        "WD_%=:\n\t"
        "}" :: "r"(bar), "r"(parity) : "memory");
}
__device__ __forceinline__ void bulk_g2s(uint32_t dst, const void* src,
                                         uint32_t bytes, uint32_t bar) {
    asm volatile(
        "cp.async.bulk.shared::cta.global.mbarrier::complete_tx::bytes [%0], [%1], %2, [%3];"
        :: "r"(dst), "l"(src), "r"(bytes), "r"(bar) : "memory");
}

// Stream flat rows [rs, re) (single batch b) through the TMA smem ring,
// accumulate, flush with REDG atomics, finalize b if we complete it.
__device__ __forceinline__ void process_range(
    char* smem, const float* __restrict__ feats, const float* __restrict__ mask,
    float* __restrict__ out, int b, int rs, int re, int tid, int d4, int sg)
{
    const int n      = re - rs;
    const int ntiles = (n + TROWS - 1) / TROWS;
    const uint32_t smb   = smem_u32(smem);
    const uint32_t feat0 = smb + SM_FEAT;
    const uint32_t bar0  = smb + SM_MBAR;

    if (tid == 0) {
#pragma unroll
        for (int s = 0; s < NST; ++s) mbar_init(bar0 + s * 8, 1);
    }
    __syncthreads();

    // Prologue: fill the ring
    if (tid == 0) {
        const int pre = ntiles < NST ? ntiles : NST;
        for (int t = 0; t < pre; ++t) {
            const int trows = (t == ntiles - 1) ? (n - t * TROWS) : TROWS;
            const uint32_t bytes = (uint32_t)trows * DD * 4;
            mbar_expect_tx(bar0 + t * 8, bytes);
            bulk_g2s(feat0 + t * TBYTES,
                     feats + (size_t)(rs + t * TROWS) * DD, bytes, bar0 + t * 8);
        }
    }

    float4 sum = make_float4(0.f, 0.f, 0.f, 0.f);
    float4 mx  = make_float4(neg_inf(), neg_inf(), neg_inf(), neg_inf());
    float  cnt = 0.f;

    for (int t = 0; t < ntiles; ++t) {
        const int slot  = t % NST;
        const int ph    = (t / NST) & 1;
        const int trows = (t == ntiles - 1) ? (n - t * TROWS) : TROWS;
        const int r0    = rs + t * TROWS;

        mbar_wait(bar0 + slot * 8, ph);

        const float4* __restrict__ fs =
            reinterpret_cast<const float4*>(smem + SM_FEAT + slot * TBYTES);
#pragma unroll
        for (int it = 0; it < TROWS / 4; ++it) {
            const int rl = it * 4 + sg;
            if (rl < trows) {
                const float  m = __ldca(mask + r0 + rl);
                const float4 f = fs[rl * 64 + d4];
                const bool   v = (m > 0.f);
                cnt += m;
                sum.x += f.x * m;  sum.y += f.y * m;
                sum.z += f.z * m;  sum.w += f.w * m;
                mx.x = fmaxf(mx.x, v ? f.x : neg_inf());
                mx.y = fmaxf(mx.y, v ? f.y : neg_inf());
                mx.z = fmaxf(mx.z, v ? f.z : neg_inf());
                mx.w = fmaxf(mx.w, v ? f.w : neg_inf());
            }
        }
        __syncthreads();   // whole CTA done reading this slot

        if (tid == 0 && t + NST < ntiles) {
            const int t2     = t + NST;
            const int t2rows = (t2 == ntiles - 1) ? (n - t2 * TROWS) : TROWS;
            const uint32_t bytes = (uint32_t)t2rows * DD * 4;
            mbar_expect_tx(bar0 + slot * 8, bytes);
            bulk_g2s(feat0 + slot * TBYTES,
                     feats + (size_t)(rs + t2 * TROWS) * DD, bytes, bar0 + slot * 8);
        }
    }

    // CTA reduce: 4 sg-groups -> 1 (64 float4 lanes remain)
    float4* s_sum  = reinterpret_cast<float4*>(smem + SM_SUM);
    float4* s_max  = reinterpret_cast<float4*>(smem + SM_MAX);
    float*  s_cnt  = reinterpret_cast<float*>(smem + SM_CNT);
    int*    s_last = reinterpret_cast<int*>(smem + SM_LAST);
    s_sum[tid] = sum;
    s_max[tid] = mx;
    if (d4 == 0) s_cnt[sg] = cnt;
    __syncthreads();

    if (tid < 64) {
        float4 a = s_sum[tid];
        float4 m = s_max[tid];
#pragma unroll
        for (int k = 1; k < 4; ++k) {
            float4 a2 = s_sum[tid + 64 * k];
            float4 m2 = s_max[tid + 64 * k];
            a.x += a2.x; a.y += a2.y; a.z += a2.z; a.w += a2.w;
            m.x = fmaxf(m.x, m2.x); m.y = fmaxf(m.y, m2.y);
            m.z = fmaxf(m.z, m2.z); m.w = fmaxf(m.w, m2.w);
        }
        const int dbase = b * DD + tid * 4;
        atomicAdd(&g_sum[dbase + 0], a.x);
        atomicAdd(&g_sum[dbase + 1], a.y);
        atomicAdd(&g_sum[dbase + 2], a.z);
        atomicAdd(&g_sum[dbase + 3], a.w);
        atomicMax(&g_maxo[dbase + 0], f2o(m.x));
        atomicMax(&g_maxo[dbase + 1], f2o(m.y));
        atomicMax(&g_maxo[dbase + 2], f2o(m.z));
        atomicMax(&g_maxo[dbase + 3], f2o(m.w));
        if (tid == 0)
            atomicAdd(&g_cnt[b], s_cnt[0] + s_cnt[1] + s_cnt[2] + s_cnt[3]);
    }

    __threadfence();
    __syncthreads();
    if (tid == 0) {
        int prev = atomicAdd(&g_rows[b], n);
        *s_last = (prev + n == SS);
    }
    __syncthreads();

    if (*s_last) {
        const int d = tid;  // 0..255
        float    fsum = __ldcg(&g_sum[b * DD + d]);
        unsigned mo   = __ldcg(&g_maxo[b * DD + d]);
        float    fcnt = __ldcg(&g_cnt[b]);
        out[(size_t)b * (2 * DD) + d]      = o2f(mo);
        out[(size_t)b * (2 * DD) + DD + d] = fsum / fcnt;
        __stcg(&g_sum[b * DD + d], 0.f);
        __stcg(&g_maxo[b * DD + d], 0u);
        if (tid == 0) {
            __stcg(&g_cnt[b], 0.f);
            __stcg(&g_rows[b], 0);
        }
    }
    __syncthreads();   // protect smem/barrier reuse by a following range
}

__global__ void __launch_bounds__(256)
pool_tma(const float* __restrict__ feats,
         const float* __restrict__ mask,
         float* __restrict__ out) {
    extern __shared__ char smem[];
    const int c   = blockIdx.x;
    const int tid = threadIdx.x;
    const int d4  = tid & 63;
    const int sg  = tid >> 6;

    const int R0    = TOTROWS / GRIDX;   // 862
    const int rem   = TOTROWS % GRIDX;   // 48
    const int start = c * R0 + min(c, rem);
    const int nrows = R0 + (c < rem ? 1 : 0);
    const int end   = start + nrows;

    // Range (<=863 rows) spans at most 2 batches (each b is 2048 rows)
    const int b0     = start / SS;
    const int b0_end = min(end, (b0 + 1) * SS);
    process_range(smem, feats, mask, out, b0, start, b0_end, tid, d4, sg);
    if (b0_end < end)
        process_range(smem, feats, mask, out, b0 + 1, b0_end, end, tid, d4, sg);
}

extern "C" void kernel_launch(void* const* d_in, const int* in_sizes, int n_in,
                              void* d_out, int out_size) {
    const float* feats = (const float*)d_in[0];
    const float* mask  = (const float*)d_in[1];
    float* out = (float*)d_out;

    cudaFuncSetAttribute(pool_tma, cudaFuncAttributeMaxDynamicSharedMemorySize, SM_TOTAL);
    pool_tma<<<GRIDX, 256, SM_TOTAL>>>(feats, mask, out);
}

// round 7
// speedup vs baseline: 1.9013x; 1.9013x over previous
#include <cuda_runtime.h>

// Problem shape (fixed by the reference)
#define BB 64
#define SS 2048
#define DD 256
#define NSPLIT 32
#define CHUNK (SS / NSPLIT)   // 64 rows of S per CTA
#define BATCH 8               // explicit in-flight float4 loads per thread

// Global scratch (statically zero-initialized; reset by the finalizing CTA each
// call so graph replays see a clean state).
__device__ float    g_sum [BB * DD];
__device__ unsigned g_maxo[BB * DD];   // order-preserving uint encoding; 0 <= f2o(x)
__device__ float    g_cnt [BB];
__device__ int      g_arrived[BB];

__device__ __forceinline__ float neg_inf() { return __int_as_float(0xff800000); }

// Monotone float <-> uint mapping so atomicMax(unsigned) == float max.
__device__ __forceinline__ unsigned f2o(float f) {
    unsigned u = __float_as_uint(f);
    return (u & 0x80000000u) ? ~u : (u | 0x80000000u);
}
__device__ __forceinline__ float o2f(unsigned u) {
    return __uint_as_float((u & 0x80000000u) ? (u & 0x7fffffffu) : ~u);
}

// One CTA per (split, b). 256 threads: d4 = tid % 64 (float4 lane over D=256),
// sg = tid / 64 (4 s-rows in parallel). Mask index depends only on sg, so the
// chunk-skip branch is warp-uniform. Rows whose mask is 0 contribute nothing to
// either reduction, so chunks with all-zero mask skip their feats loads
// entirely (exact for any mask; huge win for prefix masks).
__global__ void __launch_bounds__(256, 4)
pool_skip(const float* __restrict__ feats,
          const float* __restrict__ mask,
          float* __restrict__ out) {
    const int split = blockIdx.x;
    const int b     = blockIdx.y;
    const int tid   = threadIdx.x;
    const int d4    = tid & 63;
    const int sg    = tid >> 6;

    const int s0 = split * CHUNK;
    const float4* __restrict__ p =
        reinterpret_cast<const float4*>(feats) + ((size_t)b * SS + s0 + sg) * 64 + d4;
    const float* __restrict__ mp = mask + (size_t)b * SS + s0 + sg;

    float4 sum = make_float4(0.f, 0.f, 0.f, 0.f);
    float4 mx  = make_float4(neg_inf(), neg_inf(), neg_inf(), neg_inf());
    float  cnt = 0.f;

#pragma unroll
    for (int batch = 0; batch < CHUNK / (4 * BATCH); ++batch) {   // 2 iterations
        float mbuf[BATCH];
#pragma unroll
        for (int j = 0; j < BATCH; ++j) mbuf[j] = __ldca(mp + j * 4);

        bool allv = true, anyv = false;
#pragma unroll
        for (int j = 0; j < BATCH; ++j) {
            const bool v = (mbuf[j] > 0.f);
            allv &= v;
            anyv |= v;
        }

        if (allv) {
            // Interior of the valid prefix: no selects needed for max.
            float4 fbuf[BATCH];
#pragma unroll
            for (int j = 0; j < BATCH; ++j) fbuf[j] = __ldcs(p + j * 4 * 64);
#pragma unroll
            for (int j = 0; j < BATCH; ++j) {
                const float  m = mbuf[j];
                const float4 f = fbuf[j];
                cnt += m;
                sum.x += f.x * m;  sum.y += f.y * m;
                sum.z += f.z * m;  sum.w += f.w * m;
                mx.x = fmaxf(mx.x, f.x);
                mx.y = fmaxf(mx.y, f.y);
                mx.z = fmaxf(mx.z, f.z);
                mx.w = fmaxf(mx.w, f.w);
            }
        } else if (anyv) {
            // Boundary chunk: per-element select.
            float4 fbuf[BATCH];
#pragma unroll
            for (int j = 0; j < BATCH; ++j) fbuf[j] = __ldcs(p + j * 4 * 64);
#pragma unroll
            for (int j = 0; j < BATCH; ++j) {
                const float  m = mbuf[j];
                const float4 f = fbuf[j];
                const bool   v = (m > 0.f);
                cnt += m;
                sum.x += f.x * m;  sum.y += f.y * m;
                sum.z += f.z * m;  sum.w += f.w * m;
                mx.x = fmaxf(mx.x, v ? f.x : neg_inf());
                mx.y = fmaxf(mx.y, v ? f.y : neg_inf());
                mx.z = fmaxf(mx.z, v ? f.z : neg_inf());
                mx.w = fmaxf(mx.w, v ? f.w : neg_inf());
            }
        }
        // else: fully-masked chunk — skip feats loads entirely.

        mp += 4 * BATCH;
        p  += (size_t)4 * BATCH * 64;
    }

    // CTA-level reduce: 4 sg-groups -> 1 (64 float4 lanes remain)
    __shared__ float4 s_sum[256];
    __shared__ float4 s_max[256];
    __shared__ float  s_cnt[4];
    s_sum[tid] = sum;
    s_max[tid] = mx;
    if (d4 == 0) s_cnt[sg] = cnt;
    __syncthreads();

    if (tid < 64) {
        float4 a = s_sum[tid];
        float4 m = s_max[tid];
#pragma unroll
        for (int k = 1; k < 4; ++k) {
            float4 a2 = s_sum[tid + 64 * k];
            float4 m2 = s_max[tid + 64 * k];
            a.x += a2.x; a.y += a2.y; a.z += a2.z; a.w += a2.w;
            m.x = fmaxf(m.x, m2.x); m.y = fmaxf(m.y, m2.y);
            m.z = fmaxf(m.z, m2.z); m.w = fmaxf(m.w, m2.w);
        }
        // Fire-and-forget reductions into per-(b,d) accumulators (REDG)
        const int dbase = b * DD + tid * 4;
        atomicAdd(&g_sum[dbase + 0], a.x);
        atomicAdd(&g_sum[dbase + 1], a.y);
        atomicAdd(&g_sum[dbase + 2], a.z);
        atomicAdd(&g_sum[dbase + 3], a.w);
        atomicMax(&g_maxo[dbase + 0], f2o(m.x));
        atomicMax(&g_maxo[dbase + 1], f2o(m.y));
        atomicMax(&g_maxo[dbase + 2], f2o(m.z));
        atomicMax(&g_maxo[dbase + 3], f2o(m.w));
        if (tid == 0)
            atomicAdd(&g_cnt[b], s_cnt[0] + s_cnt[1] + s_cnt[2] + s_cnt[3]);
    }

    // Threadfence-reduction pattern: order our REDGs before the arrival counter.
    __threadfence();
    __syncthreads();
    __shared__ int s_last;
    if (tid == 0) {
        int prev = atomicAdd(&g_arrived[b], 1);
        s_last = (prev == NSPLIT - 1);
    }
    __syncthreads();
    if (!s_last) return;

    // Last CTA for this b: accumulators are final. Write output, reset scratch.
    {
        const int d = tid;  // 0..255
        float    fsum = __ldcg(&g_sum[b * DD + d]);
        unsigned mo   = __ldcg(&g_maxo[b * DD + d]);
        float    fcnt = __ldcg(&g_cnt[b]);
        out[(size_t)b * (2 * DD) + d]      = o2f(mo);
        out[(size_t)b * (2 * DD) + DD + d] = fsum / fcnt;
        __stcg(&g_sum[b * DD + d], 0.f);
        __stcg(&g_maxo[b * DD + d], 0u);
        if (tid == 0) {
            __stcg(&g_cnt[b], 0.f);
            __stcg(&g_arrived[b], 0);
        }
    }
}

extern "C" void kernel_launch(void* const* d_in, const int* in_sizes, int n_in,
                              void* d_out, int out_size) {
    const float* feats = (const float*)d_in[0];
    const float* mask  = (const float*)d_in[1];
    float* out = (float*)d_out;

    dim3 grid(NSPLIT, BB);
    pool_skip<<<grid, 256>>>(feats, mask, out);
}

// round 8
// speedup vs baseline: 2.9461x; 1.5496x over previous
#include <cuda_runtime.h>

// Problem shape (fixed by the reference)
#define BB 64
#define SS 2048
#define DD 256
#define NSPLIT 16
#define CHUNK (SS / NSPLIT)   // 128 rows of S per CTA
#define BATCH 8               // explicit in-flight float4 loads per thread
#define NSUB (CHUNK / (4 * BATCH))   // 4 sub-batches of 32 rows

// Global scratch (statically zero-initialized; reset by the finalizing CTA each
// call so graph replays see a clean state).
__device__ float    g_sum [BB * DD];
__device__ unsigned g_maxo[BB * DD];   // order-preserving uint encoding; 0 <= f2o(x)
__device__ float    g_cnt [BB];
__device__ int      g_arrived[BB];

__device__ __forceinline__ float neg_inf() { return __int_as_float(0xff800000); }

// Monotone float <-> uint mapping so atomicMax(unsigned) == float max.
__device__ __forceinline__ unsigned f2o(float f) {
    unsigned u = __float_as_uint(f);
    return (u & 0x80000000u) ? ~u : (u | 0x80000000u);
}
__device__ __forceinline__ float o2f(unsigned u) {
    return __uint_as_float((u & 0x80000000u) ? (u & 0x7fffffffu) : ~u);
}

// Arrival counter with acq_rel semantics: release orders this CTA's prior REDG
// flushes (sequenced via the preceding __syncthreads); acquire on the final
// arrival makes all other CTAs' flushes visible to the finalizer.
__device__ __forceinline__ int arrive_acq_rel(int* addr) {
    int old;
    asm volatile("atom.add.acq_rel.gpu.global.s32 %0, [%1], 1;"
                 : "=r"(old) : "l"(addr) : "memory");
    return old;
}

// One CTA per (split, b). 256 threads: d4 = tid % 64 (float4 lane over D=256),
// sg = tid / 64 (4 s-rows in parallel). Mask addresses are warp-uniform, so the
// 32-row sub-batch skip is divergence-free. Fully-masked sub-batches skip their
// feats loads entirely (exact for any mask).
__global__ void __launch_bounds__(256, 4)
pool_skip(const float* __restrict__ feats,
          const float* __restrict__ mask,
          float* __restrict__ out) {
    const int split = blockIdx.x;
    const int b     = blockIdx.y;
    const int tid   = threadIdx.x;
    const int d4    = tid & 63;
    const int sg    = tid >> 6;

    const int s0 = split * CHUNK;
    const float4* __restrict__ p =
        reinterpret_cast<const float4*>(feats) + ((size_t)b * SS + s0 + sg) * 64 + d4;
    const float* __restrict__ mp = mask + (size_t)b * SS + s0 + sg;

    float4 sum = make_float4(0.f, 0.f, 0.f, 0.f);
    float4 mx  = make_float4(neg_inf(), neg_inf(), neg_inf(), neg_inf());
    float  cnt = 0.f;

#pragma unroll
    for (int batch = 0; batch < NSUB; ++batch) {   // 4 x 32 rows
        float mbuf[BATCH];
#pragma unroll
        for (int j = 0; j < BATCH; ++j) mbuf[j] = __ldca(mp + j * 4);

        bool allv = true, anyv = false;
#pragma unroll
        for (int j = 0; j < BATCH; ++j) {
            const bool v = (mbuf[j] > 0.f);
            allv &= v;
            anyv |= v;
        }

        if (allv) {
            // Interior of the valid prefix: no selects needed for max.
            float4 fbuf[BATCH];
#pragma unroll
            for (int j = 0; j < BATCH; ++j) fbuf[j] = __ldcs(p + j * 4 * 64);
#pragma unroll
            for (int j = 0; j < BATCH; ++j) {
                const float  m = mbuf[j];
                const float4 f = fbuf[j];
                cnt += m;
                sum.x += f.x * m;  sum.y += f.y * m;
                sum.z += f.z * m;  sum.w += f.w * m;
                mx.x = fmaxf(mx.x, f.x);
                mx.y = fmaxf(mx.y, f.y);
                mx.z = fmaxf(mx.z, f.z);
                mx.w = fmaxf(mx.w, f.w);
            }
        } else if (anyv) {
            // Boundary sub-batch: per-element select.
            float4 fbuf[BATCH];
#pragma unroll
            for (int j = 0; j < BATCH; ++j) fbuf[j] = __ldcs(p + j * 4 * 64);
#pragma unroll
            for (int j = 0; j < BATCH; ++j) {
                const float  m = mbuf[j];
                const float4 f = fbuf[j];
                const bool   v = (m > 0.f);
                cnt += m;
                sum.x += f.x * m;  sum.y += f.y * m;
                sum.z += f.z * m;  sum.w += f.w * m;
                mx.x = fmaxf(mx.x, v ? f.x : neg_inf());
                mx.y = fmaxf(mx.y, v ? f.y : neg_inf());
                mx.z = fmaxf(mx.z, v ? f.z : neg_inf());
                mx.w = fmaxf(mx.w, v ? f.w : neg_inf());
            }
        }
        // else: fully-masked sub-batch — skip the feats loads entirely.

        mp += 4 * BATCH;
        p  += (size_t)4 * BATCH * 64;
    }

    // CTA-level reduce: 4 sg-groups -> 1 (64 float4 lanes remain)
    __shared__ float4 s_sum[256];
    __shared__ float4 s_max[256];
    __shared__ float  s_cnt[4];
    s_sum[tid] = sum;
    s_max[tid] = mx;
    if (d4 == 0) s_cnt[sg] = cnt;
    __syncthreads();

    if (tid < 64) {
        float4 a = s_sum[tid];
        float4 m = s_max[tid];
#pragma unroll
        for (int k = 1; k < 4; ++k) {
            float4 a2 = s_sum[tid + 64 * k];
            float4 m2 = s_max[tid + 64 * k];
            a.x += a2.x; a.y += a2.y; a.z += a2.z; a.w += a2.w;
            m.x = fmaxf(m.x, m2.x); m.y = fmaxf(m.y, m2.y);
            m.z = fmaxf(m.z, m2.z); m.w = fmaxf(m.w, m2.w);
        }
        // Fire-and-forget reductions into per-(b,d) accumulators (REDG)
        const int dbase = b * DD + tid * 4;
        atomicAdd(&g_sum[dbase + 0], a.x);
        atomicAdd(&g_sum[dbase + 1], a.y);
        atomicAdd(&g_sum[dbase + 2], a.z);
        atomicAdd(&g_sum[dbase + 3], a.w);
        atomicMax(&g_maxo[dbase + 0], f2o(m.x));
        atomicMax(&g_maxo[dbase + 1], f2o(m.y));
        atomicMax(&g_maxo[dbase + 2], f2o(m.z));
        atomicMax(&g_maxo[dbase + 3], f2o(m.w));
        if (tid == 0)
            atomicAdd(&g_cnt[b], s_cnt[0] + s_cnt[1] + s_cnt[2] + s_cnt[3]);
    }

    // Arrival: syncthreads orders every thread's REDGs before tid0's acq_rel add.
    __syncthreads();
    __shared__ int s_last;
    if (tid == 0)
        s_last = (arrive_acq_rel(&g_arrived[b]) == NSPLIT - 1);
    __syncthreads();
    if (!s_last) return;

    // Last CTA for this b: accumulators are final (acquire above). Write output,
    // reset scratch for the next graph replay.
    {
        const int d = tid;  // 0..255
        float    fsum = __ldcg(&g_sum[b * DD + d]);
        unsigned mo   = __ldcg(&g_maxo[b * DD + d]);
        float    fcnt = __ldcg(&g_cnt[b]);
        out[(size_t)b * (2 * DD) + d]      = o2f(mo);
        out[(size_t)b * (2 * DD) + DD + d] = fsum / fcnt;
        __stcg(&g_sum[b * DD + d], 0.f);
        __stcg(&g_maxo[b * DD + d], 0u);
        if (tid == 0) {
            __stcg(&g_cnt[b], 0.f);
            __stcg(&g_arrived[b], 0);
        }
    }
}

extern "C" void kernel_launch(void* const* d_in, const int* in_sizes, int n_in,
                              void* d_out, int out_size) {
    const float* feats = (const float*)d_in[0];
    const float* mask  = (const float*)d_in[1];
    float* out = (float*)d_out;

    dim3 grid(NSPLIT, BB);
    pool_skip<<<grid, 256>>>(feats, mask, out);
}